// round 6
// baseline (speedup 1.0000x reference)
#include <cuda_runtime.h>
#include <cuda_bf16.h>
#include <cstdint>

#define BB 32
#define CC 64
#define HH 64
#define WW 64
#define EE 8
#define HWC (HH*WW)

// Scratch (device globals: no allocation allowed)
__device__ float g_S[BB * 9 * CC];   // box sums, layout [(b*9+k)*C + c], k = di*3+dj
__device__ float g_val[BB];
__device__ int   g_idx[BB];

// ===========================================================================
// helpers
// ===========================================================================
__device__ __forceinline__ uint32_t smem_u32(const void* p) {
    uint32_t a;
    asm("{ .reg .u64 t; cvta.to.shared.u64 t, %1; cvt.u32.u64 %0, t; }" : "=r"(a) : "l"(p));
    return a;
}

// pack two floats -> bf16x2 word: low 16 bits = 'even', high = 'odd'
__device__ __forceinline__ uint32_t pack_bf16x2(float even, float odd) {
    uint32_t u;
    asm("cvt.rn.bf16x2.f32 %0, %1, %2;" : "=r"(u) : "f"(odd), "f"(even));
    return u;
}

// split float2 into bf16x2 hi word + bf16x2 residual word
__device__ __forceinline__ void split_pair(float2 w, uint32_t& hi, uint32_t& lo) {
    hi = pack_bf16x2(w.x, w.y);
    float hx = __uint_as_float(hi << 16);
    float hy = __uint_as_float(hi & 0xffff0000u);
    lo = pack_bf16x2(w.x - hx, w.y - hy);
}

#define LDMATRIX_X2T(R, addr) \
    asm volatile("ldmatrix.sync.aligned.m8n8.x2.trans.shared.b16 {%0,%1}, [%2];" \
        : "=r"((R)[0]), "=r"((R)[1]) : "r"(addr))

#define MMA_BF16(D, A, B0, B1) \
    asm volatile("mma.sync.aligned.m16n8k16.row.col.f32.bf16.bf16.f32 " \
        "{%0,%1,%2,%3}, {%4,%5,%6,%7}, {%8,%9}, {%0,%1,%2,%3};" \
        : "+f"((D)[0]), "+f"((D)[1]), "+f"((D)[2]), "+f"((D)[3]) \
        : "r"((A)[0]), "r"((A)[1]), "r"((A)[2]), "r"((A)[3]), "r"(B0), "r"(B1))

// ===========================================================================
// Kernel 1: box sums, coalesced + high occupancy.
// Block = one (b,c) image; 256 threads; thread loads float4 at i*256+tid
// (warp instr = 512B contiguous). Only 4 live float4 -> ~36 regs -> occ ~75%.
// ===========================================================================
__global__ __launch_bounds__(256) void region_sums_kernel(const float* __restrict__ x) {
    const int tid = threadIdx.x;
    const float4* base = (const float4*)(x + (size_t)blockIdx.x * HWC);
    float4 v[4];
    #pragma unroll
    for (int i = 0; i < 4; i++) v[i] = base[i * 256 + tid];

    const int g  = tid >> 4;   // 0..15 ; rows touched = i*16 + g
    const int c4 = tid & 15;   // float4 within row

    __shared__ float sRow[4][16];  // partial sums of edge rows 0,1,62,63
    __shared__ float sRE[4][4];    // edge row elems: x[r][0],[1],[62],[63]
    __shared__ float sCol[4][16];  // per-g partials of cols 0,1,62,63
    __shared__ float sG[8];        // per-warp grand totals

    float ps[4], gsum = 0.f;
    #pragma unroll
    for (int i = 0; i < 4; i++) {
        ps[i] = (v[i].x + v[i].y) + (v[i].z + v[i].w);
        gsum += ps[i];
    }
    // edge rows: 0=(i0,g0), 1=(i0,g1), 62=(i3,g14), 63=(i3,g15)
    if (g == 0)  sRow[0][c4] = ps[0];
    if (g == 1)  sRow[1][c4] = ps[0];
    if (g == 14) sRow[2][c4] = ps[3];
    if (g == 15) sRow[3][c4] = ps[3];
    if (c4 == 0) {
        float cl0 = (v[0].x + v[1].x) + (v[2].x + v[3].x);
        float cl1 = (v[0].y + v[1].y) + (v[2].y + v[3].y);
        sCol[0][g] = cl0; sCol[1][g] = cl1;
        if (g == 0)  { sRE[0][0] = v[0].x; sRE[0][1] = v[0].y; }
        if (g == 1)  { sRE[1][0] = v[0].x; sRE[1][1] = v[0].y; }
        if (g == 14) { sRE[2][0] = v[3].x; sRE[2][1] = v[3].y; }
        if (g == 15) { sRE[3][0] = v[3].x; sRE[3][1] = v[3].y; }
    }
    if (c4 == 15) {
        float cr0 = (v[0].z + v[1].z) + (v[2].z + v[3].z);
        float cr1 = (v[0].w + v[1].w) + (v[2].w + v[3].w);
        sCol[2][g] = cr0; sCol[3][g] = cr1;
        if (g == 0)  { sRE[0][2] = v[0].z; sRE[0][3] = v[0].w; }
        if (g == 1)  { sRE[1][2] = v[0].z; sRE[1][3] = v[0].w; }
        if (g == 14) { sRE[2][2] = v[3].z; sRE[2][3] = v[3].w; }
        if (g == 15) { sRE[3][2] = v[3].z; sRE[3][3] = v[3].w; }
    }
    #pragma unroll
    for (int o = 16; o; o >>= 1) gsum += __shfl_xor_sync(0xffffffffu, gsum, o);
    if ((tid & 31) == 0) sG[tid >> 5] = gsum;
    __syncthreads();

    if (tid < 9) {
        int di = tid / 3, dj = tid - di * 3;
        float G = 0.f;
        #pragma unroll
        for (int j = 0; j < 8; j++) G += sG[j];
        float c0 = 0.f, c1 = 0.f, c62 = 0.f, c63 = 0.f;
        #pragma unroll
        for (int j = 0; j < 16; j++) {
            c0 += sCol[0][j]; c1 += sCol[1][j]; c62 += sCol[2][j]; c63 += sCol[3][j];
        }
        float colc = (dj == 0) ? (c62 + c63) : (dj == 1) ? (c0 + c63) : (c0 + c1);
        float T = G - colc;                 // sum of cv_dj over all 64 rows
        float rw[4];
        #pragma unroll
        for (int er = 0; er < 4; er++) {
            float s = 0.f;
            #pragma unroll
            for (int j = 0; j < 16; j++) s += sRow[er][j];
            float ec = (dj == 0) ? (sRE[er][2] + sRE[er][3])
                     : (dj == 1) ? (sRE[er][0] + sRE[er][3])
                                 : (sRE[er][0] + sRE[er][1]);
            rw[er] = s - ec;                // cv_dj of that edge row
        }
        float sub = (di == 0) ? (rw[2] + rw[3])
                  : (di == 1) ? (rw[0] + rw[3])
                              : (rw[0] + rw[1]);
        int b = blockIdx.x >> 6, c = blockIdx.x & 63;
        g_S[(b * 9 + tid) * CC + c] = T - sub;
    }
}

// ===========================================================================
// Kernel 2: gating dot products, softmax, top-1, expert_weights output.
// ===========================================================================
__global__ __launch_bounds__(256) void gate_kernel(const float* __restrict__ gate_w,
                                                   const float* __restrict__ gate_b,
                                                   float* __restrict__ ew_out,
                                                   int write_ew) {
    int b = blockIdx.x;
    int tid = threadIdx.x;
    __shared__ float Ssh[9 * 64];          // [k*64 + c]
    __shared__ float gat[8];

    for (int i = tid; i < 576; i += 256) Ssh[i] = g_S[b*576 + i];
    __syncthreads();

    int warp = tid >> 5, lane = tid & 31;  // warp = expert index
    float acc = 0.f;
    for (int idx = lane; idx < 576; idx += 32) {
        int c = idx / 9;
        int k = idx - c * 9;
        acc += gate_w[warp * 576 + idx] * Ssh[k * 64 + c];
    }
    #pragma unroll
    for (int o = 16; o; o >>= 1) acc += __shfl_down_sync(0xffffffffu, acc, o);
    if (lane == 0) gat[warp] = acc + gate_b[warp] * 3844.0f;  // 62*62 positions
    __syncthreads();

    if (tid == 0) {
        float m = gat[0]; int mi = 0;
        #pragma unroll
        for (int e = 1; e < 8; e++) { if (gat[e] > m) { m = gat[e]; mi = e; } }
        float s = 0.f;
        #pragma unroll
        for (int e = 0; e < 8; e++) s += expf(gat[e] - m);
        g_val[b] = 1.0f / s;
        g_idx[b] = mi;
    }
    __syncthreads();
    if (write_ew && tid < 8) {
        ew_out[b * 8 + tid] = (tid == g_idx[b]) ? g_val[b] : 0.0f;
    }
}

// ===========================================================================
// Kernel 3: mma.sync bf16x3 GEMM, single-stage.
//   out[b,f,hw] = val[b] * sum_c W[e,f,c] * x[b,c,hw]
//   A = W: fragments built DIRECTLY from gmem (L2-hot, 16KB) into registers.
//   B = X: full 64-c tile staged once in smem (hi/lo), ldmatrix.x2.trans.
//   One __syncthreads total; mainloop = pure LDSM + HMMA.
// Block: 128 threads (4 warps: wf in {0,1} x wn in {0,1}); tile f=64 x hw=128.
// ===========================================================================
#define XPITCH 68u   // words per X row (128 bf16 data = 64 words + 4 pad); 68 % 8 == 4 -> conflict-free

__global__ __launch_bounds__(128) void moe_gemm_kernel(const float* __restrict__ x,
                                                       const float* __restrict__ expert_w,
                                                       float* __restrict__ out) {
    __shared__ uint32_t sX[2][64 * XPITCH];   // [hi/lo][c][hw-pairs]

    const int tid  = threadIdx.x;
    const int warp = tid >> 5, lane = tid & 31;
    const int wf   = warp >> 1;         // 0..1 : f group of 32
    const int wn   = warp & 1;          // 0..1 : hw group of 64
    const int b    = blockIdx.y;
    const int hw0  = blockIdx.x * 128;

    const int   e   = g_idx[b];
    const float val = g_val[b];

    const uint32_t sxh = smem_u32(sX[0]);
    const uint32_t sxl = smem_u32(sX[1]);

    // ---- stage X: full K (64 c rows), hi/lo bf16 split ----
    const float* Xsrc = x + (size_t)b * CC * HWC + hw0;
    #pragma unroll
    for (int i = 0; i < 32; i++) {
        int p = tid + i * 128;           // pair index 0..4095
        int c = p >> 6, hp = p & 63;
        float2 xv = *(const float2*)(Xsrc + (size_t)c * HWC + hp * 2);
        uint32_t hi, lo;
        split_pair(xv, hi, lo);
        sX[0][c * XPITCH + hp] = hi;
        sX[1][c * XPITCH + hp] = lo;
    }

    // ---- A fragments straight from gmem (W is 16KB, L2-resident) ----
    // m16n8k16 A layout: a0=(r, k0..k0+1) a1=(r+8, k0..) a2=(r, k0+8..) a3=(r+8, k0+8..)
    uint32_t aH[2][4][4], aL[2][4][4];
    {
        const float* Wb = expert_w + (size_t)e * 4096;
        int rA = wf * 32 + (lane >> 2);
        int kA = (lane & 3) * 2;
        #pragma unroll
        for (int mt = 0; mt < 2; mt++) {
            int r0 = rA + mt * 16;
            #pragma unroll
            for (int kt = 0; kt < 4; kt++) {
                int k0 = kt * 16 + kA;
                float2 w0 = *(const float2*)(Wb + r0 * 64 + k0);
                float2 w1 = *(const float2*)(Wb + (r0 + 8) * 64 + k0);
                float2 w2 = *(const float2*)(Wb + r0 * 64 + k0 + 8);
                float2 w3 = *(const float2*)(Wb + (r0 + 8) * 64 + k0 + 8);
                split_pair(w0, aH[mt][kt][0], aL[mt][kt][0]);
                split_pair(w1, aH[mt][kt][1], aL[mt][kt][1]);
                split_pair(w2, aH[mt][kt][2], aL[mt][kt][2]);
                split_pair(w3, aH[mt][kt][3], aL[mt][kt][3]);
            }
        }
    }

    float acc[2][8][4];
    #pragma unroll
    for (int mt = 0; mt < 2; mt++)
        #pragma unroll
        for (int nt = 0; nt < 8; nt++)
            #pragma unroll
            for (int q = 0; q < 4; q++) acc[mt][nt][q] = 0.f;

    __syncthreads();   // X tile visible

    // ---- mainloop: 4 k-tiles x 8 n-tiles, no syncs, no gmem ----
    const uint32_t krow = (uint32_t)(lane & 15);
    #pragma unroll
    for (int kt = 0; kt < 4; kt++) {
        uint32_t kbase = ((uint32_t)(kt * 16) + krow) * (XPITCH * 4u);
        #pragma unroll
        for (int nt = 0; nt < 8; nt++) {
            uint32_t noff = (uint32_t)(wn * 64 + nt * 8) * 2u;
            uint32_t bh[2], bl[2];
            LDMATRIX_X2T(bh, sxh + kbase + noff);
            LDMATRIX_X2T(bl, sxl + kbase + noff);
            #pragma unroll
            for (int mt = 0; mt < 2; mt++) {
                MMA_BF16(acc[mt][nt], aH[mt][kt], bh[0], bh[1]);
                MMA_BF16(acc[mt][nt], aH[mt][kt], bl[0], bl[1]);
                MMA_BF16(acc[mt][nt], aL[mt][kt], bh[0], bh[1]);
            }
        }
    }

    // ---- epilogue: streaming stores (output written once, never re-read) ----
    float* outb = out + (size_t)b * CC * HWC + hw0;
    int rbase = wf * 32 + (lane >> 2);
    int cbase = wn * 64 + (lane & 3) * 2;
    #pragma unroll
    for (int mt = 0; mt < 2; mt++) {
        #pragma unroll
        for (int nt = 0; nt < 8; nt++) {
            int f0 = rbase + mt * 16;
            int cc = cbase + nt * 8;
            float2 v0 = make_float2(acc[mt][nt][0] * val, acc[mt][nt][1] * val);
            float2 v1 = make_float2(acc[mt][nt][2] * val, acc[mt][nt][3] * val);
            __stcs((float2*)(outb + (size_t)f0 * HWC + cc),       v0);
            __stcs((float2*)(outb + (size_t)(f0 + 8) * HWC + cc), v1);
        }
    }
}

// ===========================================================================
extern "C" void kernel_launch(void* const* d_in, const int* in_sizes, int n_in,
                              void* d_out, int out_size) {
    const float* x = nullptr, *gate_w = nullptr, *gate_b = nullptr, *expert_w = nullptr;
    for (int i = 0; i < n_in; i++) {
        switch (in_sizes[i]) {
            case BB*CC*HH*WW: x        = (const float*)d_in[i]; break;  // 524288
            case EE*CC*3*3:   gate_w   = (const float*)d_in[i]; break;  // 4608
            case EE:          gate_b   = (const float*)d_in[i]; break;  // 8
            case EE*CC*CC:    expert_w = (const float*)d_in[i]; break;  // 32768
            default: break;
        }
    }
    float* out = (float*)d_out;
    const int main_elems = BB * CC * HH * WW;
    int write_ew = (out_size >= main_elems + BB * EE) ? 1 : 0;

    region_sums_kernel<<<BB * CC, 256>>>(x);
    gate_kernel<<<BB, 256>>>(gate_w, gate_b, out + main_elems, write_ew);
    moe_gemm_kernel<<<dim3(HWC / 128, BB), 128>>>(x, expert_w, out);
}

// round 7
// speedup vs baseline: 1.0519x; 1.0519x over previous
#include <cuda_runtime.h>
#include <cuda_fp16.h>
#include <cstdint>

#define BB 32
#define CC 64
#define HH 64
#define WW 64
#define EE 8
#define HWC (HH*WW)

// Scratch (device globals: no allocation allowed)
__device__ float g_S[BB * 9 * CC];   // box sums, layout [(b*9+k)*C + c], k = di*3+dj
__device__ float g_val[BB];
__device__ int   g_idx[BB];

// ===========================================================================
// helpers
// ===========================================================================
__device__ __forceinline__ uint32_t smem_u32(const void* p) {
    uint32_t a;
    asm("{ .reg .u64 t; cvta.to.shared.u64 t, %1; cvt.u32.u64 %0, t; }" : "=r"(a) : "l"(p));
    return a;
}

// pack two floats -> f16x2 word: low 16 bits = 'even', high = 'odd'
__device__ __forceinline__ uint32_t pack_f16x2(float even, float odd) {
    __half2 h = __floats2half2_rn(even, odd);   // .x = lo, .y = hi
    return *reinterpret_cast<uint32_t*>(&h);
}

#define LDMATRIX_X2T(R, addr) \
    asm volatile("ldmatrix.sync.aligned.m8n8.x2.trans.shared.b16 {%0,%1}, [%2];" \
        : "=r"((R)[0]), "=r"((R)[1]) : "r"(addr))

#define MMA_F16(D, A, B0, B1) \
    asm volatile("mma.sync.aligned.m16n8k16.row.col.f32.f16.f16.f32 " \
        "{%0,%1,%2,%3}, {%4,%5,%6,%7}, {%8,%9}, {%0,%1,%2,%3};" \
        : "+f"((D)[0]), "+f"((D)[1]), "+f"((D)[2]), "+f"((D)[3]) \
        : "r"((A)[0]), "r"((A)[1]), "r"((A)[2]), "r"((A)[3]), "r"(B0), "r"(B1))

// ===========================================================================
// Kernel 1: box sums, 2 images per block (halves barrier/tail count).
// Block = images {2*blk, 2*blk+1}; 256 threads; 8 independent LDG.128/thread.
// ===========================================================================
__global__ __launch_bounds__(256) void region_sums_kernel(const float* __restrict__ x) {
    const int tid = threadIdx.x;
    const float4* base0 = (const float4*)(x + (size_t)(blockIdx.x * 2) * HWC);
    const float4* base1 = (const float4*)(x + (size_t)(blockIdx.x * 2 + 1) * HWC);
    float4 va[4], vb[4];
    #pragma unroll
    for (int i = 0; i < 4; i++) va[i] = base0[i * 256 + tid];
    #pragma unroll
    for (int i = 0; i < 4; i++) vb[i] = base1[i * 256 + tid];

    const int g  = tid >> 4;   // 0..15 ; rows touched = i*16 + g
    const int c4 = tid & 15;   // float4 within row

    __shared__ float sRow[2][4][16];  // edge-row partial sums (rows 0,1,62,63)
    __shared__ float sRE[2][4][4];    // edge row elems x[r][0],[1],[62],[63]
    __shared__ float sCol[2][4][16];  // per-g partials of cols 0,1,62,63
    __shared__ float sG[2][8];        // per-warp grand totals

    #pragma unroll
    for (int m = 0; m < 2; m++) {
        float4* v = m ? vb : va;
        float ps[4], gsum = 0.f;
        #pragma unroll
        for (int i = 0; i < 4; i++) {
            ps[i] = (v[i].x + v[i].y) + (v[i].z + v[i].w);
            gsum += ps[i];
        }
        if (g == 0)  sRow[m][0][c4] = ps[0];
        if (g == 1)  sRow[m][1][c4] = ps[0];
        if (g == 14) sRow[m][2][c4] = ps[3];
        if (g == 15) sRow[m][3][c4] = ps[3];
        if (c4 == 0) {
            float cl0 = (v[0].x + v[1].x) + (v[2].x + v[3].x);
            float cl1 = (v[0].y + v[1].y) + (v[2].y + v[3].y);
            sCol[m][0][g] = cl0; sCol[m][1][g] = cl1;
            if (g == 0)  { sRE[m][0][0] = v[0].x; sRE[m][0][1] = v[0].y; }
            if (g == 1)  { sRE[m][1][0] = v[0].x; sRE[m][1][1] = v[0].y; }
            if (g == 14) { sRE[m][2][0] = v[3].x; sRE[m][2][1] = v[3].y; }
            if (g == 15) { sRE[m][3][0] = v[3].x; sRE[m][3][1] = v[3].y; }
        }
        if (c4 == 15) {
            float cr0 = (v[0].z + v[1].z) + (v[2].z + v[3].z);
            float cr1 = (v[0].w + v[1].w) + (v[2].w + v[3].w);
            sCol[m][2][g] = cr0; sCol[m][3][g] = cr1;
            if (g == 0)  { sRE[m][0][2] = v[0].z; sRE[m][0][3] = v[0].w; }
            if (g == 1)  { sRE[m][1][2] = v[0].z; sRE[m][1][3] = v[0].w; }
            if (g == 14) { sRE[m][2][2] = v[3].z; sRE[m][2][3] = v[3].w; }
            if (g == 15) { sRE[m][3][2] = v[3].z; sRE[m][3][3] = v[3].w; }
        }
        #pragma unroll
        for (int o = 16; o; o >>= 1) gsum += __shfl_xor_sync(0xffffffffu, gsum, o);
        if ((tid & 31) == 0) sG[m][tid >> 5] = gsum;
    }
    __syncthreads();

    if (tid < 18) {
        int m = tid / 9, k = tid - m * 9;
        int di = k / 3, dj = k - di * 3;
        float G = 0.f;
        #pragma unroll
        for (int j = 0; j < 8; j++) G += sG[m][j];
        float c0 = 0.f, c1 = 0.f, c62 = 0.f, c63 = 0.f;
        #pragma unroll
        for (int j = 0; j < 16; j++) {
            c0 += sCol[m][0][j]; c1 += sCol[m][1][j]; c62 += sCol[m][2][j]; c63 += sCol[m][3][j];
        }
        float colc = (dj == 0) ? (c62 + c63) : (dj == 1) ? (c0 + c63) : (c0 + c1);
        float T = G - colc;                 // sum of cv_dj over all 64 rows
        float rw[4];
        #pragma unroll
        for (int er = 0; er < 4; er++) {
            float s = 0.f;
            #pragma unroll
            for (int j = 0; j < 16; j++) s += sRow[m][er][j];
            float ec = (dj == 0) ? (sRE[m][er][2] + sRE[m][er][3])
                     : (dj == 1) ? (sRE[m][er][0] + sRE[m][er][3])
                                 : (sRE[m][er][0] + sRE[m][er][1]);
            rw[er] = s - ec;                // cv_dj of that edge row
        }
        float sub = (di == 0) ? (rw[2] + rw[3])
                  : (di == 1) ? (rw[0] + rw[3])
                              : (rw[0] + rw[1]);
        int bc = blockIdx.x * 2 + m;
        int b = bc >> 6, c = bc & 63;
        g_S[(b * 9 + k) * CC + c] = T - sub;
    }
}

// ===========================================================================
// Kernel 2: gating dot products, softmax, top-1, expert_weights output.
// ===========================================================================
__global__ __launch_bounds__(256) void gate_kernel(const float* __restrict__ gate_w,
                                                   const float* __restrict__ gate_b,
                                                   float* __restrict__ ew_out,
                                                   int write_ew) {
    int b = blockIdx.x;
    int tid = threadIdx.x;
    __shared__ float Ssh[9 * 64];          // [k*64 + c]
    __shared__ float gat[8];

    for (int i = tid; i < 576; i += 256) Ssh[i] = g_S[b*576 + i];
    __syncthreads();

    int warp = tid >> 5, lane = tid & 31;  // warp = expert index
    float acc = 0.f;
    for (int idx = lane; idx < 576; idx += 32) {
        int c = idx / 9;
        int k = idx - c * 9;
        acc += gate_w[warp * 576 + idx] * Ssh[k * 64 + c];
    }
    #pragma unroll
    for (int o = 16; o; o >>= 1) acc += __shfl_down_sync(0xffffffffu, acc, o);
    if (lane == 0) gat[warp] = acc + gate_b[warp] * 3844.0f;  // 62*62 positions
    __syncthreads();

    if (tid == 0) {
        float m = gat[0]; int mi = 0;
        #pragma unroll
        for (int e = 1; e < 8; e++) { if (gat[e] > m) { m = gat[e]; mi = e; } }
        float s = 0.f;
        #pragma unroll
        for (int e = 0; e < 8; e++) s += expf(gat[e] - m);
        g_val[b] = 1.0f / s;
        g_idx[b] = mi;
    }
    __syncthreads();
    if (write_ew && tid < 8) {
        ew_out[b * 8 + tid] = (tid == g_idx[b]) ? g_val[b] : 0.0f;
    }
}

// ===========================================================================
// Kernel 3: mma.sync fp16 GEMM (single-pass; fp16 eps 2^-11 -> rel_err ~1e-4).
//   out[b,f,hw] = val[b] * sum_c W[e,f,c] * x[b,c,hw]
//   A = W fp16 fragments built directly from gmem (L2-hot) into registers.
//   B = X fp16 tile staged once in smem, ldmatrix.x2.trans.
//   Mainloop: 64 HMMA/warp (was 192 with bf16x3) -> memory-bound, not issue-bound.
// Block: 128 threads (4 warps: wf x wn); tile f=64 x hw=128.
// ===========================================================================
#define XPITCH 68u   // words per X row (64 data words + 4 pad); stride%8=4 -> conflict-free

__global__ __launch_bounds__(128) void moe_gemm_kernel(const float* __restrict__ x,
                                                       const float* __restrict__ expert_w,
                                                       float* __restrict__ out) {
    __shared__ uint32_t sX[64 * XPITCH];   // 17.4 KB, fp16x2 words

    const int tid  = threadIdx.x;
    const int warp = tid >> 5, lane = tid & 31;
    const int wf   = warp >> 1;         // 0..1 : f group of 32
    const int wn   = warp & 1;          // 0..1 : hw group of 64
    const int b    = blockIdx.y;
    const int hw0  = blockIdx.x * 128;

    const int   e   = g_idx[b];
    const float val = g_val[b];

    const uint32_t sxb = smem_u32(sX);

    // ---- stage X: full K (64 c rows) as fp16, float4-granular coalesced ----
    const float* Xsrc = x + (size_t)b * CC * HWC + hw0;
    #pragma unroll
    for (int i = 0; i < 16; i++) {
        int idx = tid + i * 128;            // float4 index 0..2047
        int c = idx >> 5, q = idx & 31;     // row c, float4 q within row
        float4 v = *(const float4*)(Xsrc + (size_t)c * HWC + q * 4);
        uint2 w;
        w.x = pack_f16x2(v.x, v.y);
        w.y = pack_f16x2(v.z, v.w);
        *(uint2*)(sX + c * XPITCH + q * 2) = w;
    }

    // ---- A fragments (fp16 W) straight from gmem ----
    // m16n8k16 A: a0=(r,k0..k0+1) a1=(r+8,..) a2=(r,k0+8..) a3=(r+8,k0+8..)
    uint32_t af[2][4][4];
    {
        const float* Wb = expert_w + (size_t)e * 4096;
        int rA = wf * 32 + (lane >> 2);
        int kA = (lane & 3) * 2;
        #pragma unroll
        for (int mt = 0; mt < 2; mt++) {
            int r0 = rA + mt * 16;
            #pragma unroll
            for (int kt = 0; kt < 4; kt++) {
                int k0 = kt * 16 + kA;
                float2 w0 = *(const float2*)(Wb + r0 * 64 + k0);
                float2 w1 = *(const float2*)(Wb + (r0 + 8) * 64 + k0);
                float2 w2 = *(const float2*)(Wb + r0 * 64 + k0 + 8);
                float2 w3 = *(const float2*)(Wb + (r0 + 8) * 64 + k0 + 8);
                af[mt][kt][0] = pack_f16x2(w0.x, w0.y);
                af[mt][kt][1] = pack_f16x2(w1.x, w1.y);
                af[mt][kt][2] = pack_f16x2(w2.x, w2.y);
                af[mt][kt][3] = pack_f16x2(w3.x, w3.y);
            }
        }
    }

    float acc[2][8][4];
    #pragma unroll
    for (int mt = 0; mt < 2; mt++)
        #pragma unroll
        for (int nt = 0; nt < 8; nt++)
            #pragma unroll
            for (int q = 0; q < 4; q++) acc[mt][nt][q] = 0.f;

    __syncthreads();   // X tile visible

    // ---- mainloop: 4 k-tiles x 8 n-tiles; 1 LDSM + 2 HMMA per (kt,nt) ----
    const uint32_t krow = (uint32_t)(lane & 15);
    #pragma unroll
    for (int kt = 0; kt < 4; kt++) {
        uint32_t kbase = ((uint32_t)(kt * 16) + krow) * (XPITCH * 4u);
        #pragma unroll
        for (int nt = 0; nt < 8; nt++) {
            uint32_t noff = (uint32_t)(wn * 64 + nt * 8) * 2u;
            uint32_t bf[2];
            LDMATRIX_X2T(bf, sxb + kbase + noff);
            #pragma unroll
            for (int mt = 0; mt < 2; mt++)
                MMA_F16(acc[mt][nt], af[mt][kt], bf[0], bf[1]);
        }
    }

    // ---- epilogue: streaming stores (output written once, never re-read) ----
    float* outb = out + (size_t)b * CC * HWC + hw0;
    int rbase = wf * 32 + (lane >> 2);
    int cbase = wn * 64 + (lane & 3) * 2;
    #pragma unroll
    for (int mt = 0; mt < 2; mt++) {
        #pragma unroll
        for (int nt = 0; nt < 8; nt++) {
            int f0 = rbase + mt * 16;
            int cc = cbase + nt * 8;
            float2 v0 = make_float2(acc[mt][nt][0] * val, acc[mt][nt][1] * val);
            float2 v1 = make_float2(acc[mt][nt][2] * val, acc[mt][nt][3] * val);
            __stcs((float2*)(outb + (size_t)f0 * HWC + cc),       v0);
            __stcs((float2*)(outb + (size_t)(f0 + 8) * HWC + cc), v1);
        }
    }
}

// ===========================================================================
extern "C" void kernel_launch(void* const* d_in, const int* in_sizes, int n_in,
                              void* d_out, int out_size) {
    const float* x = nullptr, *gate_w = nullptr, *gate_b = nullptr, *expert_w = nullptr;
    for (int i = 0; i < n_in; i++) {
        switch (in_sizes[i]) {
            case BB*CC*HH*WW: x        = (const float*)d_in[i]; break;  // 524288
            case EE*CC*3*3:   gate_w   = (const float*)d_in[i]; break;  // 4608
            case EE:          gate_b   = (const float*)d_in[i]; break;  // 8
            case EE*CC*CC:    expert_w = (const float*)d_in[i]; break;  // 32768
            default: break;
        }
    }
    float* out = (float*)d_out;
    const int main_elems = BB * CC * HH * WW;
    int write_ew = (out_size >= main_elems + BB * EE) ? 1 : 0;

    region_sums_kernel<<<(BB * CC) / 2, 256>>>(x);
    gate_kernel<<<BB, 256>>>(gate_w, gate_b, out + main_elems, write_ew);
    moe_gemm_kernel<<<dim3(HWC / 128, BB), 128>>>(x, expert_w, out);
}